// round 12
// baseline (speedup 1.0000x reference)
#include <cuda_runtime.h>
#include <math.h>

// ---------------- problem constants ----------------
#define L_SEQ   2048
#define D_MODEL 1024
#define D_INNER 2048
#define D_STATE 16
#define D_CONV  4
#define DT_RANK 64
#define NCHUNK  16
#define CHUNK   128

// ---------------- scratch (no allocations allowed) ----------------
__device__ float g_u0[L_SEQ * D_INNER];     // in-proj output (pre-conv)
__device__ float g_gate[L_SEQ * D_INNER];   // gate-proj output (pre-silu)
__device__ float g_u[L_SEQ * D_INNER];      // post conv+silu
__device__ float g_t[L_SEQ * DT_RANK];      // dt low-rank
__device__ float g_delta[L_SEQ * D_INNER];  // softplus dt
__device__ float g_y[L_SEQ * D_INNER];      // pre out-proj
// chunked scan state
__device__ float g_hS[NCHUNK * D_INNER * 16];
__device__ float g_pS[NCHUNK * D_INNER * 16];
__device__ float g_hin[NCHUNK * D_INNER * 16];

// ---------------- generic 128x128 SIMT fp32 GEMM (R1, proven) ----------------
#define BM 128
#define BN 128
#define BK 8
#define TM 8
#define TN 8

__global__ __launch_bounds__(256, 2)
void gemm128(const float* __restrict__ A, const float* __restrict__ B,
             const float* __restrict__ bias, float* __restrict__ C,
             int M, int N, int K, int epilogue /*0: bias, 1: bias+softplus*/) {
    __shared__ float As[BK][BM];   // transposed A tile
    __shared__ float Bs[BK][BN];

    const int bx = blockIdx.x;     // N tiles
    const int by = blockIdx.y;     // M tiles
    const int tid = threadIdx.x;

    const float* Ab = A + (size_t)by * BM * K;
    const float* Bb = B + (size_t)bx * BN;

    const int arow  = tid >> 1;          // 0..127
    const int acol4 = (tid & 1) * 4;     // 0 or 4
    const int brow  = tid >> 5;          // 0..7
    const int bcol4 = (tid & 31) * 4;    // 0..124

    const int tr = tid >> 4;             // 0..15
    const int tc = tid & 15;             // 0..15

    float acc[TM][TN];
    #pragma unroll
    for (int i = 0; i < TM; i++)
        #pragma unroll
        for (int j = 0; j < TN; j++) acc[i][j] = 0.f;

    for (int k0 = 0; k0 < K; k0 += BK) {
        float4 a4 = *(const float4*)(Ab + (size_t)arow * K + k0 + acol4);
        As[acol4 + 0][arow] = a4.x;
        As[acol4 + 1][arow] = a4.y;
        As[acol4 + 2][arow] = a4.z;
        As[acol4 + 3][arow] = a4.w;
        float4 b4 = *(const float4*)(Bb + (size_t)(k0 + brow) * N + bcol4);
        *(float4*)&Bs[brow][bcol4] = b4;
        __syncthreads();

        #pragma unroll
        for (int kk = 0; kk < BK; kk++) {
            float ar[TM], br[TN];
            #pragma unroll
            for (int i = 0; i < TM; i++) ar[i] = As[kk][tr * TM + i];
            #pragma unroll
            for (int j = 0; j < TN; j++) br[j] = Bs[kk][tc * TN + j];
            #pragma unroll
            for (int i = 0; i < TM; i++)
                #pragma unroll
                for (int j = 0; j < TN; j++)
                    acc[i][j] = fmaf(ar[i], br[j], acc[i][j]);
        }
        __syncthreads();
    }

    #pragma unroll
    for (int i = 0; i < TM; i++) {
        int row = by * BM + tr * TM + i;
        #pragma unroll
        for (int j4 = 0; j4 < TN; j4 += 4) {
            int col = bx * BN + tc * TN + j4;
            float4 v;
            float* vp = &v.x;
            #pragma unroll
            for (int j = 0; j < 4; j++) {
                float t = acc[i][j4 + j] + bias[col + j];
                if (epilogue == 1) {
                    t = (t > 20.f) ? t : log1pf(expf(t));
                }
                vp[j] = t;
            }
            *(float4*)(C + (size_t)row * N + col) = v;
        }
    }
}

// ---------------- small GEMM for dt1 (R1, proven) ----------------
__global__ __launch_bounds__(256)
void gemm_n64(const float* __restrict__ A, const float* __restrict__ B,
              const float* __restrict__ bias, float* __restrict__ C, int K) {
    const int m = blockIdx.x * 4 + (threadIdx.x >> 6);
    const int n = threadIdx.x & 63;
    const float* Ar = A + (size_t)m * K;
    float acc = 0.f;
    #pragma unroll 4
    for (int k = 0; k < K; k += 4) {
        float a0 = Ar[k + 0], a1 = Ar[k + 1], a2 = Ar[k + 2], a3 = Ar[k + 3];
        acc = fmaf(a0, B[(k + 0) * 64 + n], acc);
        acc = fmaf(a1, B[(k + 1) * 64 + n], acc);
        acc = fmaf(a2, B[(k + 2) * 64 + n], acc);
        acc = fmaf(a3, B[(k + 3) * 64 + n], acc);
    }
    C[(size_t)m * 64 + n] = acc + bias[n];
}

// ---------------- causal depthwise conv (width 4) + SiLU (R1, proven) --------
__global__ __launch_bounds__(256)
void conv_silu(const float* __restrict__ U0, const float* __restrict__ cw,
               const float* __restrict__ cb, float* __restrict__ U) {
    int idx = blockIdx.x * blockDim.x + threadIdx.x;
    if (idx >= L_SEQ * D_INNER) return;
    int d = idx & (D_INNER - 1);
    int l = idx >> 11;
    float w0 = cw[d * 4 + 0], w1 = cw[d * 4 + 1], w2 = cw[d * 4 + 2], w3 = cw[d * 4 + 3];
    float acc = cb[d] + w3 * U0[idx];
    if (l >= 1) acc = fmaf(w2, U0[idx - D_INNER], acc);
    if (l >= 2) acc = fmaf(w1, U0[idx - 2 * D_INNER], acc);
    if (l >= 3) acc = fmaf(w0, U0[idx - 3 * D_INNER], acc);
    U[idx] = acc / (1.f + expf(-acc));
}

// ---------------- chunked 2-pass SSM scan (pure CUDA) ----------------
__global__ __launch_bounds__(256)
void scan_pass1(const float* __restrict__ delta, const float* __restrict__ u,
                const float* __restrict__ A_log, const float* __restrict__ Bm,
                float* __restrict__ hS, float* __restrict__ pS)
{
    const int tid  = threadIdx.x;
    const int n    = tid & 15;
    const int dgrp = tid >> 4;
    const int bx   = blockIdx.x;
    const int d     = (bx & 127) * 16 + dgrp;
    const int chunk = bx >> 7;

    const float A  = -expf(A_log[n]);
    const float Bn = Bm[n * D_INNER + d];
    const bool  smallA = fabsf(A) < 1e-6f;
    const float invA   = smallA ? 0.f : 1.f / A;

    float h = 0.f, p = 1.f;
    size_t idx = (size_t)(chunk * CHUNK) * D_INNER + d;
    for (int l = 0; l < CHUNK; l++) {
        float dt = delta[idx];
        float uu = u[idx];
        float dA = dt * A;
        float ab = __expf(dA);
        float ex = smallA ? dt * (1.f + 0.5f * dA) : (ab - 1.f) * invA;
        h = fmaf(ab, h, ex * Bn * uu);
        p *= ab;
        idx += D_INNER;
    }
    int o = (chunk * D_INNER + d) * 16 + n;
    hS[o] = h;
    pS[o] = p;
}

__global__ __launch_bounds__(256)
void scan_mid(const float* __restrict__ hS, const float* __restrict__ pS,
              float* __restrict__ hin)
{
    int i = blockIdx.x * 256 + threadIdx.x;
    int d = i >> 4, n = i & 15;
    float carry = 0.f;
    #pragma unroll
    for (int c = 0; c < NCHUNK; c++) {
        int o = (c * D_INNER + d) * 16 + n;
        hin[o] = carry;
        carry = fmaf(pS[o], carry, hS[o]);
    }
}

__global__ __launch_bounds__(256)
void scan_pass2(const float* __restrict__ delta, const float* __restrict__ u,
                const float* __restrict__ gpre, const float* __restrict__ A_log,
                const float* __restrict__ Bm, const float* __restrict__ Cm,
                const float* __restrict__ Dv, const float* __restrict__ hin,
                float* __restrict__ Y)
{
    const int tid  = threadIdx.x;
    const int n    = tid & 15;
    const int dgrp = tid >> 4;
    const int bx   = blockIdx.x;
    const int d     = (bx & 127) * 16 + dgrp;
    const int chunk = bx >> 7;

    const float A  = -expf(A_log[n]);
    const float Bn = Bm[n * D_INNER + d];
    const float Cn = Cm[n * D_INNER + d];
    const float Dd = Dv[d];
    const bool  smallA = fabsf(A) < 1e-6f;
    const float invA   = smallA ? 0.f : 1.f / A;

    float h = hin[(chunk * D_INNER + d) * 16 + n];
    size_t idx = (size_t)(chunk * CHUNK) * D_INNER + d;
    for (int l = 0; l < CHUNK; l++) {
        float dt = delta[idx];
        float uu = u[idx];
        float dA = dt * A;
        float ab = __expf(dA);
        float ex = smallA ? dt * (1.f + 0.5f * dA) : (ab - 1.f) * invA;
        h = fmaf(ab, h, ex * Bn * uu);
        float c = h * Cn;
        c += __shfl_xor_sync(0xffffffffu, c, 1);
        c += __shfl_xor_sync(0xffffffffu, c, 2);
        c += __shfl_xor_sync(0xffffffffu, c, 4);
        c += __shfl_xor_sync(0xffffffffu, c, 8);
        if (n == 0) {
            float gg = gpre[idx];
            float sil = gg / (1.f + expf(-gg));
            Y[idx] = (c + Dd * uu) * sil;
        }
        idx += D_INNER;
    }
}

// ---------------- launcher (R1 order) ----------------
extern "C" void kernel_launch(void* const* d_in, const int* in_sizes, int n_in,
                              void* d_out, int out_size)
{
    const float* x      = (const float*)d_in[0];
    const float* in_w   = (const float*)d_in[1];
    const float* in_b   = (const float*)d_in[2];
    const float* conv_w = (const float*)d_in[3];
    const float* conv_b = (const float*)d_in[4];
    const float* A_log  = (const float*)d_in[5];
    const float* B_mat  = (const float*)d_in[6];
    const float* C_mat  = (const float*)d_in[7];
    const float* D_vec  = (const float*)d_in[8];
    const float* gate_w = (const float*)d_in[9];
    const float* gate_b = (const float*)d_in[10];
    const float* dt1_w  = (const float*)d_in[11];
    const float* dt1_b  = (const float*)d_in[12];
    const float* dt2_w  = (const float*)d_in[13];
    const float* dt2_b  = (const float*)d_in[14];
    const float* out_w  = (const float*)d_in[15];
    const float* out_b  = (const float*)d_in[16];
    float* out = (float*)d_out;

    float *u0, *gate, *u, *t, *delta, *y, *hS, *pS, *hin;
    cudaGetSymbolAddress((void**)&u0,    g_u0);
    cudaGetSymbolAddress((void**)&gate,  g_gate);
    cudaGetSymbolAddress((void**)&u,     g_u);
    cudaGetSymbolAddress((void**)&t,     g_t);
    cudaGetSymbolAddress((void**)&delta, g_delta);
    cudaGetSymbolAddress((void**)&y,     g_y);
    cudaGetSymbolAddress((void**)&hS,    g_hS);
    cudaGetSymbolAddress((void**)&pS,    g_pS);
    cudaGetSymbolAddress((void**)&hin,   g_hin);

    // 1) in-proj: u0 = x @ in_w + in_b          (2048 x 2048, K=1024)
    gemm128<<<dim3(D_INNER / BN, L_SEQ / BM), 256>>>(x, in_w, in_b, u0,
                                                     L_SEQ, D_INNER, D_MODEL, 0);
    // 2) gate-proj: gate = x @ gate_w + gate_b
    gemm128<<<dim3(D_INNER / BN, L_SEQ / BM), 256>>>(x, gate_w, gate_b, gate,
                                                     L_SEQ, D_INNER, D_MODEL, 0);
    // 3) conv + silu
    conv_silu<<<(L_SEQ * D_INNER) / 256, 256>>>(u0, conv_w, conv_b, u);
    // 4) dt low-rank: t = u @ dt1_w + dt1_b     (2048 x 64, K=2048)
    gemm_n64<<<L_SEQ / 4, 256>>>(u, dt1_w, dt1_b, t, D_INNER);
    // 5) delta = softplus(t @ dt2_w + dt2_b)    (2048 x 2048, K=64)
    gemm128<<<dim3(D_INNER / BN, L_SEQ / BM), 256>>>(t, dt2_w, dt2_b, delta,
                                                     L_SEQ, D_INNER, DT_RANK, 1);
    // 6) chunked SSM scan + D skip + gating -> y
    scan_pass1<<<NCHUNK * (D_INNER / 16), 256>>>(delta, u, A_log, B_mat, hS, pS);
    scan_mid<<<(D_INNER * 16) / 256, 256>>>(hS, pS, hin);
    scan_pass2<<<NCHUNK * (D_INNER / 16), 256>>>(delta, u, gate, A_log, B_mat,
                                                 C_mat, D_vec, hin, y);
    // 7) out-proj: out = y @ out_w + out_b      (2048 x 1024, K=2048)
    gemm128<<<dim3(D_MODEL / BN, L_SEQ / BM), 256>>>(y, out_w, out_b, out,
                                                     L_SEQ, D_MODEL, D_INNER, 0);
}

// round 13
// speedup vs baseline: 1.8950x; 1.8950x over previous
#include <cuda_runtime.h>
#include <cuda_fp16.h>
#include <mma.h>
#include <math.h>

using namespace nvcuda;

// ---------------- problem constants ----------------
#define L_SEQ   2048
#define D_MODEL 1024
#define D_INNER 2048
#define DT_RANK 64
#define NCHUNK  16
#define CHUNK   128

// ---------------- scratch (no allocations allowed) ----------------
__device__ float g_u0[L_SEQ * D_INNER];
__device__ float g_gate[L_SEQ * D_INNER];
__device__ float g_u[L_SEQ * D_INNER];
__device__ float g_t[L_SEQ * DT_RANK];
__device__ float g_delta[L_SEQ * D_INNER];
__device__ float g_craw[L_SEQ * D_INNER];   // raw GEMM output (pre-bias)

// split fp16 activations A' = [Ah | Al]  (M x 2K)
__device__ half g_xA[L_SEQ * 2 * D_MODEL];
__device__ half g_uA[L_SEQ * 2 * D_INNER];
__device__ half g_tA[L_SEQ * 2 * DT_RANK];
__device__ half g_yA[L_SEQ * 2 * D_INNER];

// fp16 weights B' = [Bh ; Bh]  (2K x ldb)  (hi duplicated)
__device__ half g_inB[2 * D_MODEL * D_INNER];
__device__ half g_gateB[2 * D_MODEL * D_INNER];
__device__ half g_dt1B[2 * D_INNER * 128];      // N padded 64 -> 128
__device__ half g_dt2B[2 * DT_RANK * D_INNER];
__device__ half g_outB[2 * D_INNER * D_MODEL];

// chunked scan state
__device__ float g_hS[NCHUNK * D_INNER * 16];
__device__ float g_pS[NCHUNK * D_INNER * 16];
__device__ float g_hin[NCHUNK * D_INNER * 16];

// ---------------- WMMA fp16 GEMM: Craw[M,N] = A'[M,Kp] @ B'[Kp,N] -----------
// No inline assembly anywhere: wmma API + plain float4 smem staging with
// register-prefetch double buffering. 128x128 CTA tile, 8 warps of 32x64.
__global__ __launch_bounds__(256, 1)
void wgemm(const half* __restrict__ A, const half* __restrict__ B,
           float* __restrict__ Craw, int Kp, int ldb, int ldcraw)
{
    __shared__ half As[128][72];    // 64 cols + 8 pad (row = 144B, 16B-aligned)
    __shared__ half Bs[64][136];    // 128 cols + 8 pad (row = 272B)

    const int tid = threadIdx.x;
    const int wid = tid >> 5;
    const int m0 = blockIdx.y * 128;
    const int n0 = blockIdx.x * 128;
    const int warp_m = (wid & 3) * 32;
    const int warp_n = (wid >> 2) * 64;

    wmma::fragment<wmma::accumulator, 16, 16, 16, float> acc[2][4];
    #pragma unroll
    for (int mi = 0; mi < 2; mi++)
        #pragma unroll
        for (int nj = 0; nj < 4; nj++)
            wmma::fill_fragment(acc[mi][nj], 0.f);

    float4 pa[4], pb[4];

    auto gload = [&](int k0) {
        #pragma unroll
        for (int i = 0; i < 4; i++) {
            int idx = i * 256 + tid;
            int r = idx >> 3, c8 = (idx & 7) * 8;
            pa[i] = *(const float4*)(A + (size_t)(m0 + r) * Kp + k0 + c8);
        }
        #pragma unroll
        for (int i = 0; i < 4; i++) {
            int idx = i * 256 + tid;
            int r = idx >> 4, c8 = (idx & 15) * 8;
            pb[i] = *(const float4*)(B + (size_t)(k0 + r) * ldb + n0 + c8);
        }
    };
    auto sstore = [&]() {
        #pragma unroll
        for (int i = 0; i < 4; i++) {
            int idx = i * 256 + tid;
            int r = idx >> 3, c8 = (idx & 7) * 8;
            *(float4*)&As[r][c8] = pa[i];
        }
        #pragma unroll
        for (int i = 0; i < 4; i++) {
            int idx = i * 256 + tid;
            int r = idx >> 4, c8 = (idx & 15) * 8;
            *(float4*)&Bs[r][c8] = pb[i];
        }
    };

    gload(0);
    sstore();
    __syncthreads();

    for (int k0 = 0; k0 < Kp; k0 += 64) {
        if (k0 + 64 < Kp) gload(k0 + 64);   // prefetch next tile into regs

        #pragma unroll
        for (int kk = 0; kk < 4; kk++) {
            wmma::fragment<wmma::matrix_a, 16, 16, 16, half, wmma::row_major> fa[2];
            wmma::fragment<wmma::matrix_b, 16, 16, 16, half, wmma::row_major> fb[4];
            #pragma unroll
            for (int mi = 0; mi < 2; mi++)
                wmma::load_matrix_sync(fa[mi], &As[warp_m + mi * 16][kk * 16], 72);
            #pragma unroll
            for (int nj = 0; nj < 4; nj++)
                wmma::load_matrix_sync(fb[nj], &Bs[kk * 16][warp_n + nj * 16], 136);
            #pragma unroll
            for (int mi = 0; mi < 2; mi++)
                #pragma unroll
                for (int nj = 0; nj < 4; nj++)
                    wmma::mma_sync(acc[mi][nj], fa[mi], fb[nj], acc[mi][nj]);
        }
        __syncthreads();
        if (k0 + 64 < Kp) {
            sstore();
            __syncthreads();
        }
    }

    #pragma unroll
    for (int mi = 0; mi < 2; mi++)
        #pragma unroll
        for (int nj = 0; nj < 4; nj++)
            wmma::store_matrix_sync(
                Craw + (size_t)(m0 + warp_m + mi * 16) * ldcraw + n0 + warp_n + nj * 16,
                acc[mi][nj], ldcraw, wmma::mem_row_major);
}

// ---------------- epilogue: dst = raw + bias (optional softplus) -------------
__global__ __launch_bounds__(256)
void epilogue(const float* __restrict__ raw, const float* __restrict__ bias,
              float* __restrict__ dst, int Nvalid, int ldraw, int sp)
{
    int i = blockIdx.x * 256 + threadIdx.x;
    int row = i / Nvalid;
    int col = i - row * Nvalid;
    float v = raw[(size_t)row * ldraw + col] + bias[col];
    if (sp) v = (v > 20.f) ? v : log1pf(expf(v));
    dst[i] = v;
}

// ---------------- split kernels (intrinsics only) ----------------
__device__ __forceinline__ void split1(float v, half& h, half& l) {
    h = __float2half_rn(v);
    l = __float2half_rn(v - __half2float(h));
}

__global__ __launch_bounds__(256)
void split_act(const float4* __restrict__ V, half* __restrict__ O,
               int K4, int K, int total4)
{
    int i = blockIdx.x * 256 + threadIdx.x;
    if (i >= total4) return;
    int m = i / K4;
    int k = (i - m * K4) * 4;
    float4 v = V[i];
    half h0, l0, h1, l1, h2, l2, h3, l3;
    split1(v.x, h0, l0); split1(v.y, h1, l1);
    split1(v.z, h2, l2); split1(v.w, h3, l3);
    half2* p0 = (half2*)(O + (size_t)m * 2 * K + k);
    half2* p1 = (half2*)(O + (size_t)m * 2 * K + K + k);
    p0[0] = half2{h0, h1}; p0[1] = half2{h2, h3};
    p1[0] = half2{l0, l1}; p1[1] = half2{l2, l3};
}

__global__ __launch_bounds__(256)
void split_w(const float4* __restrict__ W, half* __restrict__ O,
             int N4, int N, int ldb, int K, int total4)
{
    int i = blockIdx.x * 256 + threadIdx.x;
    if (i >= total4) return;
    int k = i / N4;
    int n = (i - k * N4) * 4;
    float4 v = W[i];
    half2 h01 = {__float2half_rn(v.x), __float2half_rn(v.y)};
    half2 h23 = {__float2half_rn(v.z), __float2half_rn(v.w)};
    half2* p0 = (half2*)(O + (size_t)k * ldb + n);
    half2* p1 = (half2*)(O + (size_t)(K + k) * ldb + n);
    p0[0] = h01; p0[1] = h23;
    p1[0] = h01; p1[1] = h23;
}

__global__ __launch_bounds__(256)
void pad_dt1(half* __restrict__ O)
{
    int i = blockIdx.x * 256 + threadIdx.x;   // over 2*2048 * 32 half2 units
    int row = i >> 5;
    int c2  = (i & 31) * 2;
    ((half2*)(O + (size_t)row * 128 + 64 + c2))[0] = half2{(half)0.f, (half)0.f};
}

// ---------------- conv(width4) + SiLU + fp16 split (fused) ----------------
__global__ __launch_bounds__(256)
void conv_silu_split(const float* __restrict__ U0, const float* __restrict__ cw,
                     const float* __restrict__ cb, float* __restrict__ U,
                     half* __restrict__ UA)
{
    int idx = blockIdx.x * blockDim.x + threadIdx.x;
    if (idx >= L_SEQ * D_INNER) return;
    int d = idx & (D_INNER - 1);
    int l = idx >> 11;
    float w0 = cw[d * 4 + 0], w1 = cw[d * 4 + 1], w2 = cw[d * 4 + 2], w3 = cw[d * 4 + 3];
    float acc = cb[d] + w3 * U0[idx];
    if (l >= 1) acc = fmaf(w2, U0[idx - D_INNER], acc);
    if (l >= 2) acc = fmaf(w1, U0[idx - 2 * D_INNER], acc);
    if (l >= 3) acc = fmaf(w0, U0[idx - 3 * D_INNER], acc);
    float s = acc / (1.f + expf(-acc));
    U[idx] = s;
    half h, lo;
    split1(s, h, lo);
    size_t base = (size_t)l * 2 * D_INNER + d;
    UA[base] = h;
    UA[base + D_INNER] = lo;
}

// ---------------- chunked 2-pass SSM scan ----------------
__global__ __launch_bounds__(256)
void scan_pass1(const float* __restrict__ delta, const float* __restrict__ u,
                const float* __restrict__ A_log, const float* __restrict__ Bm,
                float* __restrict__ hS, float* __restrict__ pS)
{
    const int tid  = threadIdx.x;
    const int n    = tid & 15;
    const int dgrp = tid >> 4;
    const int bx   = blockIdx.x;
    const int d     = (bx & 127) * 16 + dgrp;
    const int chunk = bx >> 7;

    const float A  = -expf(A_log[n]);
    const float Bn = Bm[n * D_INNER + d];
    const bool  smallA = fabsf(A) < 1e-6f;
    const float invA   = smallA ? 0.f : 1.f / A;

    float h = 0.f, p = 1.f;
    size_t idx = (size_t)(chunk * CHUNK) * D_INNER + d;
    for (int l = 0; l < CHUNK; l++) {
        float dt = delta[idx];
        float uu = u[idx];
        float dA = dt * A;
        float ab = __expf(dA);
        float ex = smallA ? dt * (1.f + 0.5f * dA) : (ab - 1.f) * invA;
        h = fmaf(ab, h, ex * Bn * uu);
        p *= ab;
        idx += D_INNER;
    }
    int o = (chunk * D_INNER + d) * 16 + n;
    hS[o] = h;
    pS[o] = p;
}

__global__ __launch_bounds__(256)
void scan_mid(const float* __restrict__ hS, const float* __restrict__ pS,
              float* __restrict__ hin)
{
    int i = blockIdx.x * 256 + threadIdx.x;
    int d = i >> 4, n = i & 15;
    float carry = 0.f;
    #pragma unroll
    for (int c = 0; c < NCHUNK; c++) {
        int o = (c * D_INNER + d) * 16 + n;
        hin[o] = carry;
        carry = fmaf(pS[o], carry, hS[o]);
    }
}

__global__ __launch_bounds__(256)
void scan_pass2(const float* __restrict__ delta, const float* __restrict__ u,
                const float* __restrict__ gpre, const float* __restrict__ A_log,
                const float* __restrict__ Bm, const float* __restrict__ Cm,
                const float* __restrict__ Dv, const float* __restrict__ hin,
                half* __restrict__ YA)
{
    const int tid  = threadIdx.x;
    const int n    = tid & 15;
    const int dgrp = tid >> 4;
    const int bx   = blockIdx.x;
    const int d     = (bx & 127) * 16 + dgrp;
    const int chunk = bx >> 7;

    const float A  = -expf(A_log[n]);
    const float Bn = Bm[n * D_INNER + d];
    const float Cn = Cm[n * D_INNER + d];
    const float Dd = Dv[d];
    const bool  smallA = fabsf(A) < 1e-6f;
    const float invA   = smallA ? 0.f : 1.f / A;

    float h = hin[(chunk * D_INNER + d) * 16 + n];
    size_t idx = (size_t)(chunk * CHUNK) * D_INNER + d;
    size_t ybase = (size_t)(chunk * CHUNK) * 2 * D_INNER + d;
    for (int l = 0; l < CHUNK; l++) {
        float dt = delta[idx];
        float uu = u[idx];
        float dA = dt * A;
        float ab = __expf(dA);
        float ex = smallA ? dt * (1.f + 0.5f * dA) : (ab - 1.f) * invA;
        h = fmaf(ab, h, ex * Bn * uu);
        float c = h * Cn;
        c += __shfl_xor_sync(0xffffffffu, c, 1);
        c += __shfl_xor_sync(0xffffffffu, c, 2);
        c += __shfl_xor_sync(0xffffffffu, c, 4);
        c += __shfl_xor_sync(0xffffffffu, c, 8);
        if (n == 0) {
            float gg = gpre[idx];
            float sil = gg / (1.f + expf(-gg));
            float val = (c + Dd * uu) * sil;
            half hh, ll;
            split1(val, hh, ll);
            YA[ybase] = hh;
            YA[ybase + D_INNER] = ll;
        }
        idx += D_INNER;
        ybase += 2 * D_INNER;
    }
}

// ---------------- launcher ----------------
extern "C" void kernel_launch(void* const* d_in, const int* in_sizes, int n_in,
                              void* d_out, int out_size)
{
    const float* x      = (const float*)d_in[0];
    const float* in_w   = (const float*)d_in[1];
    const float* in_b   = (const float*)d_in[2];
    const float* conv_w = (const float*)d_in[3];
    const float* conv_b = (const float*)d_in[4];
    const float* A_log  = (const float*)d_in[5];
    const float* B_mat  = (const float*)d_in[6];
    const float* C_mat  = (const float*)d_in[7];
    const float* D_vec  = (const float*)d_in[8];
    const float* gate_w = (const float*)d_in[9];
    const float* gate_b = (const float*)d_in[10];
    const float* dt1_w  = (const float*)d_in[11];
    const float* dt1_b  = (const float*)d_in[12];
    const float* dt2_w  = (const float*)d_in[13];
    const float* dt2_b  = (const float*)d_in[14];
    const float* out_w  = (const float*)d_in[15];
    const float* out_b  = (const float*)d_in[16];
    float* out = (float*)d_out;

    float *u0, *gate, *u, *t, *delta, *craw, *hS, *pS, *hin;
    half *xA, *uA, *tA, *yA, *inB, *gateB, *dt1B, *dt2B, *outB;
    cudaGetSymbolAddress((void**)&u0, g_u0);       cudaGetSymbolAddress((void**)&gate, g_gate);
    cudaGetSymbolAddress((void**)&u, g_u);         cudaGetSymbolAddress((void**)&t, g_t);
    cudaGetSymbolAddress((void**)&delta, g_delta); cudaGetSymbolAddress((void**)&craw, g_craw);
    cudaGetSymbolAddress((void**)&hS, g_hS);       cudaGetSymbolAddress((void**)&pS, g_pS);
    cudaGetSymbolAddress((void**)&hin, g_hin);
    cudaGetSymbolAddress((void**)&xA, g_xA);       cudaGetSymbolAddress((void**)&uA, g_uA);
    cudaGetSymbolAddress((void**)&tA, g_tA);       cudaGetSymbolAddress((void**)&yA, g_yA);
    cudaGetSymbolAddress((void**)&inB, g_inB);     cudaGetSymbolAddress((void**)&gateB, g_gateB);
    cudaGetSymbolAddress((void**)&dt1B, g_dt1B);   cudaGetSymbolAddress((void**)&dt2B, g_dt2B);
    cudaGetSymbolAddress((void**)&outB, g_outB);

    // ---- weight splits (W[K,N] -> [2K,ldb], hi duplicated) ----
    split_w<<<(D_MODEL * D_INNER / 4 + 255) / 256, 256>>>((const float4*)in_w,   inB,
        D_INNER / 4, D_INNER, D_INNER, D_MODEL, D_MODEL * D_INNER / 4);
    split_w<<<(D_MODEL * D_INNER / 4 + 255) / 256, 256>>>((const float4*)gate_w, gateB,
        D_INNER / 4, D_INNER, D_INNER, D_MODEL, D_MODEL * D_INNER / 4);
    split_w<<<(D_INNER * DT_RANK / 4 + 255) / 256, 256>>>((const float4*)dt1_w,  dt1B,
        DT_RANK / 4, DT_RANK, 128, D_INNER, D_INNER * DT_RANK / 4);
    pad_dt1<<<(2 * D_INNER * 32 + 255) / 256, 256>>>(dt1B);
    split_w<<<(DT_RANK * D_INNER / 4 + 255) / 256, 256>>>((const float4*)dt2_w,  dt2B,
        D_INNER / 4, D_INNER, D_INNER, DT_RANK, DT_RANK * D_INNER / 4);
    split_w<<<(D_INNER * D_MODEL / 4 + 255) / 256, 256>>>((const float4*)out_w,  outB,
        D_MODEL / 4, D_MODEL, D_MODEL, D_INNER, D_INNER * D_MODEL / 4);

    // ---- x split ----
    split_act<<<(L_SEQ * D_MODEL / 4 + 255) / 256, 256>>>((const float4*)x, xA,
        D_MODEL / 4, D_MODEL, L_SEQ * D_MODEL / 4);

    // ---- in-proj ----
    wgemm<<<dim3(D_INNER / 128, L_SEQ / 128), 256>>>(xA, inB, craw,
                                                     2 * D_MODEL, D_INNER, D_INNER);
    epilogue<<<(L_SEQ * D_INNER) / 256, 256>>>(craw, in_b, u0, D_INNER, D_INNER, 0);
    // ---- gate-proj ----
    wgemm<<<dim3(D_INNER / 128, L_SEQ / 128), 256>>>(xA, gateB, craw,
                                                     2 * D_MODEL, D_INNER, D_INNER);
    epilogue<<<(L_SEQ * D_INNER) / 256, 256>>>(craw, gate_b, gate, D_INNER, D_INNER, 0);

    // ---- conv + silu + split (fused) ----
    conv_silu_split<<<(L_SEQ * D_INNER) / 256, 256>>>(u0, conv_w, conv_b, u, uA);

    // ---- dt1 (N padded to 128, valid 64) ----
    wgemm<<<dim3(1, L_SEQ / 128), 256>>>(uA, dt1B, craw, 2 * D_INNER, 128, 128);
    epilogue<<<(L_SEQ * DT_RANK) / 256, 256>>>(craw, dt1_b, t, DT_RANK, 128, 0);

    // ---- t split + dt2 (+softplus) ----
    split_act<<<(L_SEQ * DT_RANK / 4 + 255) / 256, 256>>>((const float4*)t, tA,
        DT_RANK / 4, DT_RANK, L_SEQ * DT_RANK / 4);
    wgemm<<<dim3(D_INNER / 128, L_SEQ / 128), 256>>>(tA, dt2B, craw,
                                                     2 * DT_RANK, D_INNER, D_INNER);
    epilogue<<<(L_SEQ * D_INNER) / 256, 256>>>(craw, dt2_b, delta, D_INNER, D_INNER, 1);

    // ---- chunked scan (pass2 emits fp16 split y directly) ----
    scan_pass1<<<NCHUNK * (D_INNER / 16), 256>>>(delta, u, A_log, B_mat, hS, pS);
    scan_mid<<<(D_INNER * 16) / 256, 256>>>(hS, pS, hin);
    scan_pass2<<<NCHUNK * (D_INNER / 16), 256>>>(delta, u, gate, A_log, B_mat,
                                                 C_mat, D_vec, hin, yA);

    // ---- out-proj ----
    wgemm<<<dim3(D_MODEL / 128, L_SEQ / 128), 256>>>(yA, outB, craw,
                                                     2 * D_INNER, D_MODEL, D_MODEL);
    epilogue<<<(L_SEQ * D_MODEL) / 256, 256>>>(craw, out_b, out, D_MODEL, D_MODEL, 0);
}